// round 5
// baseline (speedup 1.0000x reference)
#include <cuda_runtime.h>
#include <cstdint>

// Problem constants
#define Bsz   1024
#define Tt    128
#define DIN   256
#define Hh    128
#define NG    512          // 4*H gates
#define KTOT  896          // DIN + H + 4*H (x | h | 4 shuffled-h via folded read)

// ---------------- device scratch (static, no allocations) ----------------
__device__ float d_WcT[NG * KTOT];      // [n][k] combined weight (transposed: k contiguous)
__device__ float d_bias[NG];
__device__ float d_add0[NG];            // t==0 read-vector bias
__device__ float d_memsm[Hh * Hh];      // softmax(memory, axis=0)
__device__ float d_h[Bsz * Hh];
__device__ float d_c[Bsz * Hh];
__device__ float d_S[Bsz * Hh];         // sum over t of h
__device__ float d_gates[Bsz * NG];
__device__ float d_f0[2 * Hh];          // fc_w direct-h part
__device__ float d_gv[2 * 4 * Hh];      // fc_w read part folded through mem_sm

// ---------------- helpers ----------------
__device__ __forceinline__ float to_tf32(float x) {
    unsigned u;
    asm("cvt.rna.tf32.f32 %0, %1;" : "=r"(u) : "f"(x));
    return __uint_as_float(u);
}

__device__ __forceinline__ void mma8(float* d, const float* a, float b0f, float b1f) {
    asm volatile(
        "mma.sync.aligned.m16n8k8.row.col.f32.tf32.tf32.f32 "
        "{%0,%1,%2,%3}, {%4,%5,%6,%7}, {%8,%9}, {%0,%1,%2,%3};\n"
        : "+f"(d[0]), "+f"(d[1]), "+f"(d[2]), "+f"(d[3])
        : "r"(__float_as_uint(a[0])), "r"(__float_as_uint(a[1])),
          "r"(__float_as_uint(a[2])), "r"(__float_as_uint(a[3])),
          "r"(__float_as_uint(b0f)), "r"(__float_as_uint(b1f)));
}

__device__ __forceinline__ void load16(const float* p, float4* r) {
#pragma unroll
    for (int i = 0; i < 4; i++) r[i] = ((const float4*)p)[i];
}

__device__ __forceinline__ void cvt_store16(float* dst, const float4* r) {
#pragma unroll
    for (int i = 0; i < 4; i++) {
        dst[4 * i + 0] = to_tf32(r[i].x);
        dst[4 * i + 1] = to_tf32(r[i].y);
        dst[4 * i + 2] = to_tf32(r[i].z);
        dst[4 * i + 3] = to_tf32(r[i].w);
    }
}

// Source pointer for Hcat[b][k0 .. k0+31] (one 32-chunk lies fully in one segment;
// segment boundaries are at multiples of 128).
__device__ __forceinline__ const float* a_src_ptr(const float* __restrict__ x,
                                                  int b, int t, int k0) {
    int seg = k0 >> 7;                     // 0,1: x | 2: h | 3..6: shuffled h
    if (seg < 2)  return x + (b * Tt + t) * DIN + k0;
    if (seg == 2) return d_h + b * Hh + (k0 - 256);
    int j  = seg - 3;
    int bb = (4 * b + j) & (Bsz - 1);
    return d_h + bb * Hh + (k0 - 384 - 128 * j);
}

// ---------------- setup kernels ----------------

// softmax over memory slots (axis=0): one block per column w, 128 threads (one per m)
__global__ void softmax_kernel(const float* __restrict__ memory) {
    int w = blockIdx.x;
    int m = threadIdx.x;
    __shared__ float red[Hh];
    float v = memory[m * Hh + w];
    red[m] = v;
    __syncthreads();
    for (int s = 64; s > 0; s >>= 1) {
        if (m < s) red[m] = fmaxf(red[m], red[m + s]);
        __syncthreads();
    }
    float mx = red[0];
    __syncthreads();
    float e = expf(v - mx);
    red[m] = e;
    __syncthreads();
    for (int s = 64; s > 0; s >>= 1) {
        if (m < s) red[m] += red[m + s];
        __syncthreads();
    }
    d_memsm[m * Hh + w] = e / red[0];
}

// Build WcT[n][k]:
//   k <  256        : W_ih[n, k]                       (x part)
//   256 <= k < 384  : W_hh[n, k-256]                   (h part)
//   k >= 384        : A_j[n][w] = sum_m W_ih[n, 256+128j+m] * mem_sm[m, w]
__global__ void build_wct_kernel(const float* __restrict__ W_ih,
                                 const float* __restrict__ W_hh) {
    int idx = blockIdx.x * blockDim.x + threadIdx.x;
    if (idx >= NG * KTOT) return;
    int n = idx / KTOT, k = idx % KTOT;
    float v;
    if (k < 256) {
        v = W_ih[n * 768 + k];
    } else if (k < 384) {
        v = W_hh[n * Hh + (k - 256)];
    } else {
        int j = (k - 384) >> 7, w = (k - 384) & 127;
        const float* wr = W_ih + n * 768 + 256 + 128 * j;
        float s = 0.f;
#pragma unroll 8
        for (int m = 0; m < 128; m++) s += wr[m] * d_memsm[m * Hh + w];
        v = s;
    }
    d_WcT[idx] = v;
}

// bias, add0 (initial read-vector contribution), f0, gv (output projection folded)
__global__ void build_misc_kernel(const float* __restrict__ W_ih,
                                  const float* __restrict__ rv0,
                                  const float* __restrict__ b_ih,
                                  const float* __restrict__ b_hh,
                                  const float* __restrict__ fc_w) {
    int idx = blockIdx.x * blockDim.x + threadIdx.x;
    if (idx < NG) {
        d_bias[idx] = b_ih[idx] + b_hh[idx];
        const float* wr = W_ih + idx * 768 + 256;
        float s = 0.f;
#pragma unroll 8
        for (int k = 0; k < 512; k++) s += rv0[k] * wr[k];
        d_add0[idx] = s;
    } else if (idx < NG + 2 * Hh) {
        int i2 = idx - NG;
        int o = i2 >> 7, w = i2 & 127;
        d_f0[i2] = fc_w[o * 640 + w];
    } else if (idx < NG + 2 * Hh + 2 * 4 * Hh) {
        int i2 = idx - NG - 2 * Hh;                 // [o][j][w]
        int o = i2 >> 9, jw = i2 & 511;
        int j = jw >> 7, w = jw & 127;
        float s = 0.f;
#pragma unroll 8
        for (int m = 0; m < 128; m++)
            s += d_memsm[m * Hh + w] * fc_w[o * 640 + 128 + 128 * j + m];
        d_gv[i2] = s;
    }
}

__global__ void zero_state_kernel() {
    int i = blockIdx.x * blockDim.x + threadIdx.x;
    if (i < Bsz * Hh) {
        d_h[i] = 0.f;
        d_c[i] = 0.f;
        d_S[i] = 0.f;
    }
}

// ---------------- per-step GEMM: gates = Hcat @ Wc + bias (+add0 at t==0) ----------------
// C tile 64x64 per block, BK=32, 4 warps (2x2), warp tile 32x32 via m16n8k8 tf32 mma.
// Smem stride 36 floats makes all fragment loads bank-conflict-free.
__global__ void __launch_bounds__(128) gemm_gates_kernel(const float* __restrict__ x, int t) {
    __shared__ float As[2][64][36];
    __shared__ float Bs[2][64][36];   // [n][k]

    const int tid  = threadIdx.x;
    const int n0   = blockIdx.x * 64;
    const int b0   = blockIdx.y * 64;
    const int warp = tid >> 5, lane = tid & 31;
    const int wm   = (warp >> 1) * 32, wn = (warp & 1) * 32;
    const int g    = lane >> 2, t4 = lane & 3;
    const int arow = tid >> 1, acol = (tid & 1) * 16;

    float acc[2][4][4];
#pragma unroll
    for (int i = 0; i < 2; i++)
#pragma unroll
        for (int j = 0; j < 4; j++)
#pragma unroll
            for (int q = 0; q < 4; q++) acc[i][j][q] = 0.f;

    float4 ra[4], rb[4];

    // prologue: chunk 0
    load16(a_src_ptr(x, b0 + arow, t, 0) + acol, ra);
    load16(d_WcT + (n0 + arow) * KTOT + acol, rb);
    cvt_store16(&As[0][arow][acol], ra);
    cvt_store16(&Bs[0][arow][acol], rb);
    __syncthreads();

#pragma unroll 1
    for (int ck = 0; ck < 28; ck++) {
        int cur = ck & 1;
        if (ck + 1 < 28) {
            int k0 = (ck + 1) * 32;
            load16(a_src_ptr(x, b0 + arow, t, k0) + acol, ra);
            load16(d_WcT + (n0 + arow) * KTOT + k0 + acol, rb);
        }
#pragma unroll
        for (int ks = 0; ks < 4; ks++) {
            float afr[2][4];
#pragma unroll
            for (int mi = 0; mi < 2; mi++) {
                int mr = wm + mi * 16;
                afr[mi][0] = As[cur][mr + g][ks * 8 + t4];
                afr[mi][1] = As[cur][mr + g + 8][ks * 8 + t4];
                afr[mi][2] = As[cur][mr + g][ks * 8 + t4 + 4];
                afr[mi][3] = As[cur][mr + g + 8][ks * 8 + t4 + 4];
            }
#pragma unroll
            for (int ni = 0; ni < 4; ni++) {
                int nr = wn + ni * 8;
                float bf0 = Bs[cur][nr + g][ks * 8 + t4];
                float bf1 = Bs[cur][nr + g][ks * 8 + t4 + 4];
                mma8(acc[0][ni], afr[0], bf0, bf1);
                mma8(acc[1][ni], afr[1], bf0, bf1);
            }
        }
        __syncthreads();
        if (ck + 1 < 28) {
            cvt_store16(&As[cur ^ 1][arow][acol], ra);
            cvt_store16(&Bs[cur ^ 1][arow][acol], rb);
            __syncthreads();
        }
    }

    // epilogue: add bias (+add0 at t==0), write gates
#pragma unroll
    for (int mi = 0; mi < 2; mi++) {
#pragma unroll
        for (int ni = 0; ni < 4; ni++) {
            int r    = b0 + wm + mi * 16 + g;
            int cidx = n0 + wn + ni * 8 + 2 * t4;
            float bb0 = d_bias[cidx];
            float bb1 = d_bias[cidx + 1];
            if (t == 0) { bb0 += d_add0[cidx]; bb1 += d_add0[cidx + 1]; }
            d_gates[r * NG + cidx]           = acc[mi][ni][0] + bb0;
            d_gates[r * NG + cidx + 1]       = acc[mi][ni][1] + bb1;
            d_gates[(r + 8) * NG + cidx]     = acc[mi][ni][2] + bb0;
            d_gates[(r + 8) * NG + cidx + 1] = acc[mi][ni][3] + bb1;
        }
    }
}

// ---------------- per-step elementwise LSTM update ----------------
__global__ void lstm_update_kernel() {
    int idx = blockIdx.x * blockDim.x + threadIdx.x;   // b*128 + u
    if (idx >= Bsz * Hh) return;
    int b = idx >> 7, u = idx & 127;
    const float* gr = d_gates + b * NG;
    float ig = gr[u];
    float fg = gr[128 + u];
    float gg = gr[256 + u];
    float og = gr[384 + u];
    float si = 1.f / (1.f + expf(-ig));
    float sf = 1.f / (1.f + expf(-fg));
    float so = 1.f / (1.f + expf(-og));
    float c  = sf * d_c[idx] + si * tanhf(gg);
    float h  = so * tanhf(c);
    d_c[idx] = c;
    d_h[idx] = h;
    d_S[idx] += h;
}

// ---------------- final output: mean over t, linear in S ----------------
__global__ void final_out_kernel(float* __restrict__ out, const float* __restrict__ fc_b) {
    int idx = blockIdx.x * blockDim.x + threadIdx.x;   // 2048 outputs
    if (idx >= Bsz * 2) return;
    int b = idx >> 1, o = idx & 1;
    const float* Sb = d_S + b * Hh;
    const float* f0 = d_f0 + o * Hh;
    float s = 0.f;
#pragma unroll 8
    for (int w = 0; w < Hh; w++) s += Sb[w] * f0[w];
#pragma unroll
    for (int j = 0; j < 4; j++) {
        int bs = (4 * b + j) & (Bsz - 1);
        const float* Sp = d_S + bs * Hh;
        const float* gp = d_gv + o * 512 + j * Hh;
#pragma unroll 8
        for (int w = 0; w < Hh; w++) s += Sp[w] * gp[w];
    }
    out[idx] = s * (1.f / (float)Tt) + fc_b[o];
}

// ---------------- launch ----------------
extern "C" void kernel_launch(void* const* d_in, const int* in_sizes, int n_in,
                              void* d_out, int out_size) {
    const float* x      = (const float*)d_in[0];
    const float* memory = (const float*)d_in[1];
    const float* rv0    = (const float*)d_in[2];
    const float* W_ih   = (const float*)d_in[3];
    const float* W_hh   = (const float*)d_in[4];
    const float* b_ih   = (const float*)d_in[5];
    const float* b_hh   = (const float*)d_in[6];
    const float* fc_w   = (const float*)d_in[7];
    const float* fc_b   = (const float*)d_in[8];
    float* out = (float*)d_out;

    zero_state_kernel<<<(Bsz * Hh + 255) / 256, 256>>>();
    softmax_kernel<<<Hh, Hh>>>(memory);
    build_wct_kernel<<<(NG * KTOT + 255) / 256, 256>>>(W_ih, W_hh);
    build_misc_kernel<<<7, 256>>>(W_ih, rv0, b_ih, b_hh, fc_w);

    dim3 ggrid(NG / 64, Bsz / 64);   // (8, 16) = 128 blocks
    for (int t = 0; t < Tt; t++) {
        gemm_gates_kernel<<<ggrid, 128>>>(x, t);
        lstm_update_kernel<<<(Bsz * Hh + 255) / 256, 256>>>();
    }

    final_out_kernel<<<(Bsz * 2 + 255) / 256, 256>>>(out, fc_b);
}